// round 3
// baseline (speedup 1.0000x reference)
#include <cuda_runtime.h>
#include <math.h>

// Problem constants (must match reference)
#define BB 16
#define HH 120
#define WW 160
#define DD 401          // int(8000/20)+1
#define WT 4            // w-tile per block
#define NT 384          // threads per block (12 warps -> 5 blocks/SM -> 1 wave for 640 blocks)
#define NPIX (HH * WT)  // 480 pixels per block
#define NV4 ((WT * DD) / 4)  // 401 float4 in the accumulator / output span
#define DEPTH_MAX 8000.0f
#define INV_BIN   (1.0f / 20.0f)
#define BIN_SIZE  20.0f
#define ZERO_EPS  1e-06f
#define SIG_EPS   (0.5f + 1e-08f)

// fp32 sparsity: g(k) = exp(-0.5*((k*20-d)/0.5)^2)/... underflows to exactly 0
// unless |k*20 - d| < ~6.6.  Bins are 20 apart, so AT MOST the rounded-nearest
// bin k = round(d/20) can be nonzero -> one exp, one conditional atomic, and
// k is always in [0,400] for valid d in (0, 8000].  (d>eps && d<=max) also
// rejects NaN/Inf, so no isfinite needed.

__global__ void __launch_bounds__(NT)
dim_hist_kernel(const float* __restrict__ depth, float* __restrict__ out)
{
    const int blk = blockIdx.x;              // 0 .. BB*WW/WT - 1  (640)
    const int b   = blk / (WW / WT);
    const int w0  = (blk - b * (WW / WT)) * WT;
    const int tid = threadIdx.x;

    // ---- prefetch depth FIRST: LDG latency overlaps smem zero + barrier ----
    // pixel p -> h = p>>2, wi = p&3 ; consecutive tid -> consecutive w (coalesced)
    const float* dbase = depth + (size_t)b * HH * WW + w0;
    float d0 = -1.0f, d1 = -1.0f;
    {
        int p = tid;                                  // p < 480 always (tid < 384)
        if (p < NPIX) d0 = __ldg(dbase + (p >> 2) * WW + (p & 3));
        int p2 = tid + NT;
        if (p2 < NPIX) d1 = __ldg(dbase + (p2 >> 2) * WW + (p2 & 3));
    }

    __shared__ __align__(16) float acc[WT * DD];     // 6416 B

    // zero accumulator: 401 float4 stores
    float4* a4 = (float4*)acc;
    if (tid < NV4) a4[tid] = make_float4(0.f, 0.f, 0.f, 0.f);
    if (tid + NT < NV4) a4[tid + NT] = make_float4(0.f, 0.f, 0.f, 0.f);
    __syncthreads();

    const float inv_sig = 1.0f / SIG_EPS;                 // 1/(sigma+eps)
    const float norm    = 0.3989422804014327f * inv_sig;  // 1/((sigma+eps)*sqrt(2pi))

    // ---- scatter: one rounded-nearest bin per valid pixel ----
    {
        float d = d0;
        if (d > ZERO_EPS && d <= DEPTH_MAX) {           // also rejects NaN/Inf
            int k = (int)(d * INV_BIN + 0.5f);          // in [0, 400], no clamp needed
            float z = ((float)k * BIN_SIZE - d) * inv_sig;
            float g = __expf(-0.5f * z * z) * norm;
            int wi = tid & 3;
            if (g != 0.0f) atomicAdd(&acc[wi * DD + k], g);
        }
    }
    {
        float d = d1;
        if (d > ZERO_EPS && d <= DEPTH_MAX) {
            int k = (int)(d * INV_BIN + 0.5f);
            float z = ((float)k * BIN_SIZE - d) * inv_sig;
            float g = __expf(-0.5f * z * z) * norm;
            int wi = (tid + NT) & 3;
            if (g != 0.0f) atomicAdd(&acc[wi * DD + k], g);
        }
    }
    __syncthreads();

    // ---- contiguous, 16B-aligned writeout: out[b, w0..w0+3, :] = 401 float4 ----
    float4* o4 = (float4*)(out + ((size_t)b * WW + w0) * DD);
    if (tid < NV4) o4[tid] = a4[tid];
    if (tid + NT < NV4) o4[tid + NT] = a4[tid + NT];
}

extern "C" void kernel_launch(void* const* d_in, const int* in_sizes, int n_in,
                              void* d_out, int out_size)
{
    const float* depth = (const float*)d_in[0];
    float* out = (float*)d_out;
    dim_hist_kernel<<<(BB * WW) / WT, NT>>>(depth, out);
}

// round 4
// speedup vs baseline: 1.0386x; 1.0386x over previous
#include <cuda_runtime.h>
#include <math.h>

// Problem constants (must match reference)
#define BB 16
#define HH 120
#define WW 160
#define DD 401              // int(8000/20)+1
#define WT 4                // w-tile per block
#define NT 512              // 16 warps -> 4 blocks/SM -> full 64-warp occupancy, one wave
#define NPIX (HH * WT)      // 480 pixels per block  (< NT: one predicated op each)
#define NV4 ((WT * DD) / 4) // 401 float4 spans      (< NT: one predicated op each)
#define DEPTH_MAX 8000.0f
#define INV_BIN   (1.0f / 20.0f)
#define BIN_SIZE  20.0f
#define ZERO_EPS  1e-06f
#define SIG_EPS   (0.5f + 1e-08f)

// fp32 sparsity: g underflows to exactly 0 unless |k*20 - d| < ~7.2, and bins
// are 20 apart -> only the rounded-nearest bin k = round(d/20) can be nonzero.
// For valid d in (eps, 8000], k is in [0,400]: no clamp. (d>eps && d<=max)
// also rejects NaN/Inf.

__global__ void __launch_bounds__(NT)
dim_hist_kernel(const float* __restrict__ depth, float* __restrict__ out)
{
    const int blk = blockIdx.x;              // 0 .. 639
    const int b   = blk / (WW / WT);
    const int w0  = (blk - b * (WW / WT)) * WT;
    const int tid = threadIdx.x;

    // ---- one predicated LDG, issued first: latency overlaps zero + BAR ----
    // pixel p = tid -> h = p>>2, wi = p&3 ; consecutive tid -> consecutive w
    float d = -1.0f;
    if (tid < NPIX)
        d = __ldg(depth + ((size_t)b * HH + (tid >> 2)) * WW + w0 + (tid & 3));

    __shared__ __align__(16) float acc[WT * DD];     // 6416 B

    // ---- zero: one predicated STS.128 per thread ----
    float4* a4 = (float4*)acc;
    if (tid < NV4) a4[tid] = make_float4(0.f, 0.f, 0.f, 0.f);
    __syncthreads();

    const float inv_sig = 1.0f / SIG_EPS;                 // 1/(sigma+eps)
    const float norm    = 0.3989422804014327f * inv_sig;  // 1/((sigma+eps)*sqrt(2pi))

    // ---- scatter: one EX2 + at most one shared atomic per thread ----
    if (d > ZERO_EPS && d <= DEPTH_MAX) {
        int k   = __float2int_rn(d * INV_BIN);            // nearest bin, in [0,400]
        float z = ((float)k * BIN_SIZE - d) * inv_sig;
        float g = __expf(-0.5f * z * z) * norm;
        if (g != 0.0f) atomicAdd(&acc[(tid & 3) * DD + k], g);
    }
    __syncthreads();

    // ---- writeout: one LDS.128 + STG.128 per thread ----
    // out[b, w0..w0+3, :] is contiguous & 16B-aligned (4*DD*4 bytes per block)
    float4* o4 = (float4*)(out + ((size_t)b * WW + w0) * DD);
    if (tid < NV4) o4[tid] = a4[tid];
}

extern "C" void kernel_launch(void* const* d_in, const int* in_sizes, int n_in,
                              void* d_out, int out_size)
{
    const float* depth = (const float*)d_in[0];
    float* out = (float*)d_out;
    dim_hist_kernel<<<(BB * WW) / WT, NT>>>(depth, out);
}